// round 11
// baseline (speedup 1.0000x reference)
#include <cuda_runtime.h>
#include <cuda_bf16.h>
#include <cstdint>

#define HEADS 12
#define SEQ   2048
#define BATCH 4
#define DH    64
#define CDIM  768
#define MTOT  8192   // BATCH*SEQ
#define NQKV ((size_t)BATCH * HEADS * SEQ * DH)

// ---------------- scratch (allocation-free) ----------------
__device__ __align__(16) __nv_bfloat16 g_qhi[NQKV], g_qlo[NQKV];
__device__ __align__(16) __nv_bfloat16 g_khi[NQKV], g_klo[NQKV];
__device__ __align__(16) __nv_bfloat16 g_vhi[NQKV], g_vlo[NQKV];
__device__ __align__(16) __nv_bfloat16 g_a_hi[(size_t)MTOT * CDIM];
__device__ __align__(16) __nv_bfloat16 g_a_lo[(size_t)MTOT * CDIM];
__device__ __align__(16) __nv_bfloat16 g_w_hi[(size_t)3 * CDIM * CDIM];
__device__ __align__(16) __nv_bfloat16 g_w_lo[(size_t)3 * CDIM * CDIM];

// persistent-attention work-stealing state (self-resetting)
__device__ int g_work = 0;
__device__ int g_done = 0;

#define ATTN_ITEMS (32 * HEADS * BATCH)   // 1536
#define ATTN_GRID  444                    // 148 SMs x 3 CTAs

// Q prescale: 1/sqrt(64) * log2(e)
#define QSCALE 0.1803368801111204f

// ---------------- helpers ----------------
__device__ __forceinline__ uint32_t smem_u32(const void* p) {
    uint32_t a;
    asm("{ .reg .u64 t; cvta.to.shared.u64 t, %1; cvt.u32.u64 %0, t; }" : "=r"(a) : "l"(p));
    return a;
}
__device__ __forceinline__ void ldsm4(uint32_t& r0, uint32_t& r1, uint32_t& r2, uint32_t& r3,
                                      uint32_t addr) {
    asm volatile("ldmatrix.sync.aligned.m8n8.x4.shared.b16 {%0,%1,%2,%3}, [%4];"
                 : "=r"(r0), "=r"(r1), "=r"(r2), "=r"(r3) : "r"(addr));
}
__device__ __forceinline__ void ldsm4t(uint32_t& r0, uint32_t& r1, uint32_t& r2, uint32_t& r3,
                                       uint32_t addr) {
    asm volatile("ldmatrix.sync.aligned.m8n8.x4.trans.shared.b16 {%0,%1,%2,%3}, [%4];"
                 : "=r"(r0), "=r"(r1), "=r"(r2), "=r"(r3) : "r"(addr));
}
__device__ __forceinline__ void mma16816(float* c, const uint32_t* a, uint32_t b0, uint32_t b1) {
    asm volatile("mma.sync.aligned.m16n8k16.row.col.f32.bf16.bf16.f32 "
                 "{%0,%1,%2,%3}, {%4,%5,%6,%7}, {%8,%9}, {%0,%1,%2,%3};"
                 : "+f"(c[0]), "+f"(c[1]), "+f"(c[2]), "+f"(c[3])
                 : "r"(a[0]), "r"(a[1]), "r"(a[2]), "r"(a[3]), "r"(b0), "r"(b1));
}
__device__ __forceinline__ __nv_bfloat16 bhi(float x) { return __float2bfloat16(x); }
__device__ __forceinline__ __nv_bfloat16 blo(float x, __nv_bfloat16 h) {
    return __float2bfloat16(x - __bfloat162float(h));
}
__device__ __forceinline__ float ex2f(float x) {
    float y;
    asm("ex2.approx.f32 %0, %1;" : "=f"(y) : "f"(x));
    return y;
}
__device__ __forceinline__ uint32_t packbf(float lo_, float hi_) {
    uint32_t r;
    asm("cvt.rn.bf16x2.f32 %0, %1, %2;" : "=r"(r) : "f"(hi_), "f"(lo_));
    return r;
}

#define CP_ASYNC16(dst, src) \
    asm volatile("cp.async.cg.shared.global [%0], [%1], 16;" :: "r"(dst), "l"(src))
#define CP_COMMIT() asm volatile("cp.async.commit_group;")
#define CP_WAIT1()  asm volatile("cp.async.wait_group 1;")
#define CP_WAIT0()  asm volatile("cp.async.wait_group 0;")

// ---------------------------------------------------------------------------
__global__ void split_kernel(const float4* __restrict__ src,
                             __nv_bfloat162* __restrict__ hi,
                             __nv_bfloat162* __restrict__ lo, int n4)
{
    int i = blockIdx.x * 256 + threadIdx.x;
    if (i < n4) {
        float4 v = src[i];
        __nv_bfloat16 hx = __float2bfloat16(v.x);
        __nv_bfloat16 hy = __float2bfloat16(v.y);
        __nv_bfloat16 hz = __float2bfloat16(v.z);
        __nv_bfloat16 hw = __float2bfloat16(v.w);
        hi[2 * i]     = __nv_bfloat162(hx, hy);
        hi[2 * i + 1] = __nv_bfloat162(hz, hw);
        lo[2 * i]     = __nv_bfloat162(blo(v.x, hx), blo(v.y, hy));
        lo[2 * i + 1] = __nv_bfloat162(blo(v.z, hz), blo(v.w, hw));
    }
}

// ---------------------------------------------------------------------------
// HMMA bf16x3 GEMM v2 (unchanged from round 10).
// ---------------------------------------------------------------------------
#define LDT2 40
#define GM_MSZ (128 * LDT2)
#define GAHI 0
#define GALO GM_MSZ
#define GWHI (2 * GM_MSZ)
#define GWLO (3 * GM_MSZ)
#define GM_BUF (4 * GM_MSZ)
#define GEMM_SMEM (2 * GM_BUF * 2)     // 81920 bytes
#define NCHUNK 24

template <int MODE>
__global__ void __launch_bounds__(256, 2)
mma_gemm(const __nv_bfloat16* __restrict__ a_hi, const __nv_bfloat16* __restrict__ a_lo,
         const __nv_bfloat16* __restrict__ w_hi, const __nv_bfloat16* __restrict__ w_lo,
         const float* __restrict__ bias, float* __restrict__ out)
{
    extern __shared__ __nv_bfloat16 sm[];
    const uint32_t smb = smem_u32(sm);
    const int tid  = threadIdx.x;
    const int lane = tid & 31;
    const int wrp  = tid >> 5;
    const int wm   = wrp & 1;
    const int wn   = wrp >> 1;
    const int rowBase = blockIdx.y * 128;
    const int colBase = blockIdx.x * 128;

    const int a_r = lane & 15;
    const int a_k = (lane >> 4) * 8;
    const int b_r = (lane & 7) + ((lane >> 4) << 3);
    const int b_k = ((lane >> 3) & 1) * 8;

    float acc[4][4][4] = {};

    #define LOAD_CHUNK(kk, buf)                                                       \
        do {                                                                          \
            const uint32_t _bb = smb + (uint32_t)((buf) * GM_BUF) * 2;                \
            _Pragma("unroll")                                                         \
            for (int _i = 0; _i < 2; ++_i) {                                          \
                const int _idx = _i * 256 + tid;                                      \
                const int _r = _idx >> 2, _c = _idx & 3;                              \
                const size_t _ga = (size_t)(rowBase + _r) * CDIM + (kk) + _c * 8;     \
                const size_t _gw = (size_t)(colBase + _r) * CDIM + (kk) + _c * 8;     \
                const uint32_t _so = (uint32_t)(_r * LDT2 + _c * 8) * 2;              \
                CP_ASYNC16(_bb + GAHI * 2 + _so, a_hi + _ga);                         \
                CP_ASYNC16(_bb + GALO * 2 + _so, a_lo + _ga);                         \
                CP_ASYNC16(_bb + GWHI * 2 + _so, w_hi + _gw);                         \
                CP_ASYNC16(_bb + GWLO * 2 + _so, w_lo + _gw);                         \
            }                                                                         \
        } while (0)

    LOAD_CHUNK(0, 0);
    CP_COMMIT();

    for (int t = 0; t < NCHUNK; ++t) {
        const int buf = t & 1;
        __syncthreads();
        if (t < NCHUNK - 1) {
            LOAD_CHUNK((t + 1) * 32, buf ^ 1);
            CP_COMMIT();
            CP_WAIT1();
        } else {
            CP_WAIT0();
        }
        __syncthreads();

        const uint32_t ahB = smb + (uint32_t)(buf * GM_BUF + GAHI) * 2;
        const uint32_t alB = smb + (uint32_t)(buf * GM_BUF + GALO) * 2;
        const uint32_t whB = smb + (uint32_t)(buf * GM_BUF + GWHI) * 2;
        const uint32_t wlB = smb + (uint32_t)(buf * GM_BUF + GWLO) * 2;

        #pragma unroll
        for (int ks = 0; ks < 2; ++ks) {
            uint32_t ah[4][4], al[4][4], wh2[2][4], wl2[2][4];
            #pragma unroll
            for (int mt = 0; mt < 4; ++mt) {
                const uint32_t off =
                    (uint32_t)((wm * 64 + mt * 16 + a_r) * LDT2 + ks * 16 + a_k) * 2;
                ldsm4(ah[mt][0], ah[mt][1], ah[mt][2], ah[mt][3], ahB + off);
                ldsm4(al[mt][0], al[mt][1], al[mt][2], al[mt][3], alB + off);
            }
            #pragma unroll
            for (int np2 = 0; np2 < 2; ++np2) {
                const uint32_t off =
                    (uint32_t)((wn * 32 + np2 * 16 + b_r) * LDT2 + ks * 16 + b_k) * 2;
                ldsm4(wh2[np2][0], wh2[np2][1], wh2[np2][2], wh2[np2][3], whB + off);
                ldsm4(wl2[np2][0], wl2[np2][1], wl2[np2][2], wl2[np2][3], wlB + off);
            }
            #pragma unroll
            for (int mt = 0; mt < 4; ++mt)
                #pragma unroll
                for (int nt = 0; nt < 4; ++nt) {
                    const uint32_t bh0 = wh2[nt >> 1][(nt & 1) * 2];
                    const uint32_t bh1 = wh2[nt >> 1][(nt & 1) * 2 + 1];
                    const uint32_t bl0 = wl2[nt >> 1][(nt & 1) * 2];
                    const uint32_t bl1 = wl2[nt >> 1][(nt & 1) * 2 + 1];
                    mma16816(acc[mt][nt], ah[mt], bh0, bh1);
                    mma16816(acc[mt][nt], al[mt], bh0, bh1);
                    mma16816(acc[mt][nt], ah[mt], bl0, bl1);
                }
        }
    }
    #undef LOAD_CHUNK

    #pragma unroll
    for (int mt = 0; mt < 4; ++mt) {
        const int r0 = rowBase + wm * 64 + mt * 16 + (lane >> 2);
        #pragma unroll
        for (int nt = 0; nt < 4; ++nt) {
            const int c = colBase + wn * 32 + nt * 8 + (lane & 3) * 2;
            const float2 bv = *(const float2*)&bias[c];
            float vx0 = acc[mt][nt][0] + bv.x, vy0 = acc[mt][nt][1] + bv.y;
            float vx1 = acc[mt][nt][2] + bv.x, vy1 = acc[mt][nt][3] + bv.y;
            if (MODE == 0) {
                const int tsel = c / CDIM;
                const int rem  = c - tsel * CDIM;
                const int hh = rem >> 6, d = rem & 63;
                const int m0 = r0, b0 = m0 >> 11, n0 = m0 & 2047;
                const int n1 = n0 + 8;
                if (tsel == 0) { vx0 *= QSCALE; vy0 *= QSCALE; vx1 *= QSCALE; vy1 *= QSCALE; }
                __nv_bfloat16 h00 = bhi(vx0), h01 = bhi(vy0), h10 = bhi(vx1), h11 = bhi(vy1);
                __nv_bfloat16* dh = (tsel == 0) ? g_qhi : (tsel == 1) ? g_khi : g_vhi;
                __nv_bfloat16* dl = (tsel == 0) ? g_qlo : (tsel == 1) ? g_klo : g_vlo;
                const size_t i0 = (((size_t)b0 * HEADS + hh) * SEQ + n0) * DH + d;
                const size_t i1 = (((size_t)b0 * HEADS + hh) * SEQ + n1) * DH + d;
                *(__nv_bfloat162*)&dh[i0] = __nv_bfloat162(h00, h01);
                *(__nv_bfloat162*)&dl[i0] = __nv_bfloat162(blo(vx0, h00), blo(vy0, h01));
                *(__nv_bfloat162*)&dh[i1] = __nv_bfloat162(h10, h11);
                *(__nv_bfloat162*)&dl[i1] = __nv_bfloat162(blo(vx1, h10), blo(vy1, h11));
            } else {
                float2 v0, v1;
                v0.x = vx0; v0.y = vy0; v1.x = vx1; v1.y = vy1;
                *(float2*)&out[(size_t)r0 * CDIM + c] = v0;
                *(float2*)&out[(size_t)(r0 + 8) * CDIM + c] = v1;
            }
        }
    }
}

// ---------------------------------------------------------------------------
// HMMA flash attention v6: PERSISTENT work-stealing over 1536 (q0,h,b) items,
// 444 CTAs (3/SM), no wave tail. Per item Q frags re-staged via buffer 0.
// ---------------------------------------------------------------------------
#define QLD 72
#define MSZ (64 * QLD)
#define BKHI 0
#define BKLO MSZ
#define BVHI (2 * MSZ)
#define BVLO (3 * MSZ)
#define BUFSZ (4 * MSZ)
#define ATTN_SMEM (2 * BUFSZ * 2 + 16)   // 73744 bytes

__global__ void __launch_bounds__(128, 3)
attn_kernel()
{
    extern __shared__ __nv_bfloat16 sm[];
    const uint32_t smb = smem_u32(sm);
    int* sm_item = (int*)(sm + 2 * BUFSZ);

    const int tid  = threadIdx.x;
    const int lane = tid & 31;
    const int wrp  = tid >> 5;
    const int wq   = wrp * 16;

    const int a_r = lane & 15;
    const int a_k = (lane >> 4) * 8;
    const int b_r = (lane & 7) + ((lane >> 4) << 3);
    const int b_k = ((lane >> 3) & 1) * 8;
    const int v_k = (lane & 7) + (((lane >> 3) & 1) << 3);
    const int v_d = (lane >> 4) * 8;
    const int qr  = lane >> 2;
    const int qc  = (lane & 3) * 2;

    for (;;) {
        if (tid == 0) *sm_item = atomicAdd(&g_work, 1);
        __syncthreads();                 // item visible; prior item fully done
        const int idx = *sm_item;
        if (idx >= ATTN_ITEMS) break;

        const int q0 = (idx & 31) * 64;
        const int rest = idx >> 5;
        const int h = rest % HEADS;
        const int b = rest / HEADS;
        const size_t base = ((size_t)(b * HEADS + h)) * SEQ * DH;

        // ---- stage Q through buffer 0, extract fragments ----
        uint32_t qh[4][4], ql[4][4];
        {
            #pragma unroll
            for (int i = 0; i < 4; ++i) {
                const int ii = i * 128 + tid;
                const int r = ii >> 3, c8 = ii & 7;
                *(uint4*)&sm[r * QLD + c8 * 8] =
                    *(const uint4*)&g_qhi[base + (size_t)(q0 + r) * DH + c8 * 8];
                *(uint4*)&sm[MSZ + r * QLD + c8 * 8] =
                    *(const uint4*)&g_qlo[base + (size_t)(q0 + r) * DH + c8 * 8];
            }
            __syncthreads();
            #pragma unroll
            for (int ks = 0; ks < 4; ++ks) {
                ldsm4(qh[ks][0], qh[ks][1], qh[ks][2], qh[ks][3],
                      smb + (uint32_t)((wq + a_r) * QLD + ks * 16 + a_k) * 2);
                ldsm4(ql[ks][0], ql[ks][1], ql[ks][2], ql[ks][3],
                      smb + (uint32_t)(MSZ + (wq + a_r) * QLD + ks * 16 + a_k) * 2);
            }
            __syncthreads();             // Q reads done before cp.async overwrites
        }

        #define LOAD_TILE(k0, buf)                                                    \
            do {                                                                      \
                const uint32_t _bb = smb + (uint32_t)((buf) * BUFSZ) * 2;             \
                const __nv_bfloat16* _kh = g_khi + base + (size_t)(k0) * DH;          \
                const __nv_bfloat16* _kl = g_klo + base + (size_t)(k0) * DH;          \
                const __nv_bfloat16* _vh = g_vhi + base + (size_t)(k0) * DH;          \
                const __nv_bfloat16* _vl = g_vlo + base + (size_t)(k0) * DH;          \
                _Pragma("unroll")                                                     \
                for (int _i = 0; _i < 4; ++_i) {                                      \
                    const int _idx = _i * 128 + tid;                                  \
                    const int _r = _idx >> 3, _c = _idx & 7;                          \
                    const uint32_t _so = (uint32_t)(_r * QLD + _c * 8) * 2;           \
                    const size_t _go = (size_t)_r * 64 + _c * 8;                      \
                    CP_ASYNC16(_bb + BKHI * 2 + _so, _kh + _go);                      \
                    CP_ASYNC16(_bb + BKLO * 2 + _so, _kl + _go);                      \
                    CP_ASYNC16(_bb + BVHI * 2 + _so, _vh + _go);                      \
                    CP_ASYNC16(_bb + BVLO * 2 + _so, _vl + _go);                      \
                }                                                                     \
            } while (0)

        LOAD_TILE(0, 0);
        CP_COMMIT();

        float m_i[2] = {-1e30f, -1e30f};
        float l_i[2] = {0.f, 0.f};
        float oacc[8][4] = {};

        for (int t = 0; t < 32; ++t) {
            const int buf = t & 1;
            __syncthreads();
            if (t < 31) {
                LOAD_TILE((t + 1) * 64, buf ^ 1);
                CP_COMMIT();
                CP_WAIT1();
            } else {
                CP_WAIT0();
            }
            __syncthreads();

            const uint32_t kh = smb + (uint32_t)(buf * BUFSZ + BKHI) * 2;
            const uint32_t kl = smb + (uint32_t)(buf * BUFSZ + BKLO) * 2;
            const uint32_t vh = smb + (uint32_t)(buf * BUFSZ + BVHI) * 2;
            const uint32_t vl = smb + (uint32_t)(buf * BUFSZ + BVLO) * 2;

            // ---- S = QK^T ----
            float sacc[8][4] = {};
            #pragma unroll
            for (int ks = 0; ks < 4; ++ks) {
                #pragma unroll
                for (int ng = 0; ng < 4; ++ng) {
                    uint32_t bf[4];
                    ldsm4(bf[0], bf[1], bf[2], bf[3],
                          kh + (uint32_t)((ng * 16 + b_r) * QLD + ks * 16 + b_k) * 2);
                    mma16816(sacc[ng * 2 + 0], qh[ks], bf[0], bf[1]);
                    mma16816(sacc[ng * 2 + 1], qh[ks], bf[2], bf[3]);
                    mma16816(sacc[ng * 2 + 0], ql[ks], bf[0], bf[1]);
                    mma16816(sacc[ng * 2 + 1], ql[ks], bf[2], bf[3]);
                }
            }
            #pragma unroll
            for (int ks = 0; ks < 4; ++ks) {
                #pragma unroll
                for (int ng = 0; ng < 4; ++ng) {
                    uint32_t bf[4];
                    ldsm4(bf[0], bf[1], bf[2], bf[3],
                          kl + (uint32_t)((ng * 16 + b_r) * QLD + ks * 16 + b_k) * 2);
                    mma16816(sacc[ng * 2 + 0], qh[ks], bf[0], bf[1]);
                    mma16816(sacc[ng * 2 + 1], qh[ks], bf[2], bf[3]);
                }
            }

            // ---- online softmax (exp2 domain, warp-local) ----
            #pragma unroll
            for (int ri = 0; ri < 2; ++ri) {
                float mx = -1e30f;
                #pragma unroll
                for (int nt = 0; nt < 8; ++nt) {
                    mx = fmaxf(mx, sacc[nt][ri * 2 + 0]);
                    mx = fmaxf(mx, sacc[nt][ri * 2 + 1]);
                }
                mx = fmaxf(mx, __shfl_xor_sync(0xffffffffu, mx, 1));
                mx = fmaxf(mx, __shfl_xor_sync(0xffffffffu, mx, 2));
                const float mn = fmaxf(m_i[ri], mx);
                const float alpha = ex2f(m_i[ri] - mn);
                m_i[ri] = mn;
                float r = 0.f;
                #pragma unroll
                for (int nt = 0; nt < 8; ++nt) {
                    float p0 = ex2f(sacc[nt][ri * 2 + 0] - mn);
                    float p1 = ex2f(sacc[nt][ri * 2 + 1] - mn);
                    sacc[nt][ri * 2 + 0] = p0;
                    sacc[nt][ri * 2 + 1] = p1;
                    r += p0 + p1;
                }
                r += __shfl_xor_sync(0xffffffffu, r, 1);
                r += __shfl_xor_sync(0xffffffffu, r, 2);
                l_i[ri] = l_i[ri] * alpha + r;
                #pragma unroll
                for (int nt = 0; nt < 8; ++nt) {
                    oacc[nt][ri * 2 + 0] *= alpha;
                    oacc[nt][ri * 2 + 1] *= alpha;
                }
            }

            // ---- PV: P frags from sacc, V frags via ldmatrix.trans ----
            #pragma unroll
            for (int ks = 0; ks < 4; ++ks) {
                uint32_t ph[4], pl[4];
                {
                    const float s00 = sacc[2 * ks][0],     s01 = sacc[2 * ks][1];
                    const float s02 = sacc[2 * ks][2],     s03 = sacc[2 * ks][3];
                    const float s10 = sacc[2 * ks + 1][0], s11 = sacc[2 * ks + 1][1];
                    const float s12 = sacc[2 * ks + 1][2], s13 = sacc[2 * ks + 1][3];
                    ph[0] = packbf(s00, s01);
                    ph[1] = packbf(s02, s03);
                    ph[2] = packbf(s10, s11);
                    ph[3] = packbf(s12, s13);
                    pl[0] = packbf(s00 - __uint_as_float(ph[0] << 16),
                                   s01 - __uint_as_float(ph[0] & 0xffff0000u));
                    pl[1] = packbf(s02 - __uint_as_float(ph[1] << 16),
                                   s03 - __uint_as_float(ph[1] & 0xffff0000u));
                    pl[2] = packbf(s10 - __uint_as_float(ph[2] << 16),
                                   s11 - __uint_as_float(ph[2] & 0xffff0000u));
                    pl[3] = packbf(s12 - __uint_as_float(ph[3] << 16),
                                   s13 - __uint_as_float(ph[3] & 0xffff0000u));
                }
                const uint32_t vrow = (uint32_t)((ks * 16 + v_k) * QLD) * 2;
                #pragma unroll
                for (int ng = 0; ng < 4; ++ng) {
                    uint32_t bh[4], bl[4];
                    const uint32_t voff = vrow + (uint32_t)(ng * 16 + v_d) * 2;
                    ldsm4t(bh[0], bh[1], bh[2], bh[3], vh + voff);
                    ldsm4t(bl[0], bl[1], bl[2], bl[3], vl + voff);
                    mma16816(oacc[ng * 2 + 0], ph, bh[0], bh[1]);
                    mma16816(oacc[ng * 2 + 1], ph, bh[2], bh[3]);
                    mma16816(oacc[ng * 2 + 0], ph, bl[0], bl[1]);
                    mma16816(oacc[ng * 2 + 1], ph, bl[2], bl[3]);
                    mma16816(oacc[ng * 2 + 0], pl, bh[0], bh[1]);
                    mma16816(oacc[ng * 2 + 1], pl, bh[2], bh[3]);
                }
            }
        }

        // ---- epilogue: normalize, split hi/lo, write a_hi/a_lo [B,N,C] ----
        const float inv0 = 1.f / l_i[0];
        const float inv1 = 1.f / l_i[1];
        const int row0 = q0 + wq + qr;
        #pragma unroll
        for (int nt = 0; nt < 8; ++nt) {
            const int col = h * DH + nt * 8 + qc;
            const size_t i0 = ((size_t)b * SEQ + row0) * CDIM + col;
            const size_t i1 = ((size_t)b * SEQ + row0 + 8) * CDIM + col;
            float o00 = oacc[nt][0] * inv0, o01 = oacc[nt][1] * inv0;
            float o10 = oacc[nt][2] * inv1, o11 = oacc[nt][3] * inv1;
            __nv_bfloat16 h00 = bhi(o00), h01 = bhi(o01), h10 = bhi(o10), h11 = bhi(o11);
            *(__nv_bfloat162*)&g_a_hi[i0] = __nv_bfloat162(h00, h01);
            *(__nv_bfloat162*)&g_a_lo[i0] = __nv_bfloat162(blo(o00, h00), blo(o01, h01));
            *(__nv_bfloat162*)&g_a_hi[i1] = __nv_bfloat162(h10, h11);
            *(__nv_bfloat162*)&g_a_lo[i1] = __nv_bfloat162(blo(o10, h10), blo(o11, h11));
        }
        #undef LOAD_TILE
    }

    // ---- self-resetting finish protocol (last CTA zeroes counters) ----
    __syncthreads();
    if (tid == 0) {
        const int d = atomicAdd(&g_done, 1);
        if (d == ATTN_GRID - 1) {
            g_work = 0;
            __threadfence();
            g_done = 0;
        }
    }
}

// ---------------------------------------------------------------------------
extern "C" void kernel_launch(void* const* d_in, const int* in_sizes, int n_in,
                              void* d_out, int out_size)
{
    const float* x      = (const float*)d_in[0];
    const float* qkv_w  = (const float*)d_in[1];
    const float* qkv_b  = (const float*)d_in[2];
    const float* proj_w = (const float*)d_in[3];
    const float* proj_b = (const float*)d_in[4];
    float* out = (float*)d_out;

    cudaFuncSetAttribute(mma_gemm<0>, cudaFuncAttributeMaxDynamicSharedMemorySize, GEMM_SMEM);
    cudaFuncSetAttribute(mma_gemm<1>, cudaFuncAttributeMaxDynamicSharedMemorySize, GEMM_SMEM);
    cudaFuncSetAttribute(attn_kernel, cudaFuncAttributeMaxDynamicSharedMemorySize, ATTN_SMEM);

    __nv_bfloat16 *a_hi, *a_lo, *w_hi, *w_lo;
    cudaGetSymbolAddress((void**)&a_hi, g_a_hi);
    cudaGetSymbolAddress((void**)&a_lo, g_a_lo);
    cudaGetSymbolAddress((void**)&w_hi, g_w_hi);
    cudaGetSymbolAddress((void**)&w_lo, g_w_lo);

    const int nx4 = MTOT * CDIM / 4;
    const int nw4 = 3 * CDIM * CDIM / 4;
    const int np4 = CDIM * CDIM / 4;

    split_kernel<<<(nx4 + 255) / 256, 256>>>((const float4*)x,
        (__nv_bfloat162*)a_hi, (__nv_bfloat162*)a_lo, nx4);
    split_kernel<<<(nw4 + 255) / 256, 256>>>((const float4*)qkv_w,
        (__nv_bfloat162*)w_hi, (__nv_bfloat162*)w_lo, nw4);

    mma_gemm<0><<<dim3(18, 64), 256, GEMM_SMEM>>>(a_hi, a_lo, w_hi, w_lo, qkv_b, nullptr);

    attn_kernel<<<ATTN_GRID, 128, ATTN_SMEM>>>();

    split_kernel<<<(np4 + 255) / 256, 256>>>((const float4*)proj_w,
        (__nv_bfloat162*)w_hi, (__nv_bfloat162*)w_lo, np4);
    mma_gemm<1><<<dim3(6, 64), 256, GEMM_SMEM>>>(a_hi, a_lo, w_hi, w_lo, proj_b, out);
}